// round 10
// baseline (speedup 1.0000x reference)
#include <cuda_runtime.h>

// BinNormTrain: per-row nu s.t. sum_d sigmoid(x[d]+nu) == 64; out = sigmoid(x+nu).
// R10 = R8 (2-row-per-warp ILP, warm start -> Newton(analytic slope) -> one pass
// with accurate step + 2nd-order Taylor output; butterfly SHFL reductions —
// f32 redux.sync does NOT exist on sm_103) with residency fixed:
// __launch_bounds__(128, 14) caps regs at 36 so all 2048 blocks fit in ONE wave
// (14 blocks/SM x 148 = 2072), killing the 1.15-wave tail that held occ at 53%.

#ifndef BN_D
#define BN_D 256
#endif

static __device__ __forceinline__ float ex2_approx(float a) {
    float r; asm("ex2.approx.ftz.f32 %0, %1;" : "=f"(r) : "f"(a)); return r;
}
static __device__ __forceinline__ float rcp_approx(float a) {
    float r; asm("rcp.approx.ftz.f32 %0, %1;" : "=f"(r) : "f"(a)); return r;
}

// Paired butterfly reductions: independent chains, latencies overlap.
static __device__ __forceinline__ void warp_sum2(float& a, float& b) {
    #pragma unroll
    for (int o = 16; o > 0; o >>= 1) {
        a += __shfl_xor_sync(0xFFFFFFFFu, a, o);
        b += __shfl_xor_sync(0xFFFFFFFFu, b, o);
    }
}
static __device__ __forceinline__ void warp_sum4(float& a, float& b, float& c, float& d) {
    #pragma unroll
    for (int o = 16; o > 0; o >>= 1) {
        a += __shfl_xor_sync(0xFFFFFFFFu, a, o);
        b += __shfl_xor_sync(0xFFFFFFFFu, b, o);
        c += __shfl_xor_sync(0xFFFFFFFFu, c, o);
        d += __shfl_xor_sync(0xFFFFFFFFu, d, o);
    }
}

// Quad-rational sigmoids of (xs[i]+nu): 8 EX2 + 2 RCP; accumulates f (and q).
template <bool WithQ>
static __device__ __forceinline__ void sig8(const float* xs, float nl2e,
                                            float* s, float& f, float& q) {
    const float L2E = 1.44269504f;
    #pragma unroll
    for (int b = 0; b < 8; b += 4) {
        float t0 = ex2_approx(fmaf(xs[b+0], -L2E, nl2e));
        float t1 = ex2_approx(fmaf(xs[b+1], -L2E, nl2e));
        float t2 = ex2_approx(fmaf(xs[b+2], -L2E, nl2e));
        float t3 = ex2_approx(fmaf(xs[b+3], -L2E, nl2e));
        float u0 = 1.f + t0, u1 = 1.f + t1, u2 = 1.f + t2, u3 = 1.f + t3;
        float p01 = u0 * u1, p23 = u2 * u3;
        float rq  = rcp_approx(p01 * p23);
        float t01 = p23 * rq, t23 = p01 * rq;
        float s0 = u1 * t01, s1 = u0 * t01;
        float s2 = u3 * t23, s3 = u2 * t23;
        s[b+0] = s0; s[b+1] = s1; s[b+2] = s2; s[b+3] = s3;
        f += (s0 + s1) + (s2 + s3);
        if (WithQ) {
            q = fmaf(s0, s0, q); q = fmaf(s1, s1, q);
            q = fmaf(s2, s2, q); q = fmaf(s3, s3, q);
        }
    }
}

__global__ __launch_bounds__(128, 14)
void binnorm_kernel(const float* __restrict__ x, float* __restrict__ out, int B) {
    const int lane   = threadIdx.x & 31;
    const int warp0  = (blockIdx.x * blockDim.x + threadIdx.x) >> 5;
    const int nwarps = (gridDim.x * blockDim.x) >> 5;   // 8192
    const float L2E = 1.44269504f;

    // Each warp owns rows {warp0, warp0 + nwarps}; B == 2*nwarps exactly for
    // this problem (16384), guarded uniformly for safety.
    const int rowA = warp0;
    int rowB = warp0 + nwarps;
    if (rowA >= B) return;
    if (rowB >= B) rowB = rowA;            // degenerate duplicate; still correct

    const float4* __restrict__ xa = reinterpret_cast<const float4*>(x + (size_t)rowA * BN_D);
    const float4* __restrict__ xb = reinterpret_cast<const float4*>(x + (size_t)rowB * BN_D);
    float4 a0 = xa[lane], a1 = xa[lane + 32];
    float4 b0 = xb[lane], b1 = xb[lane + 32];
    float xsA[8] = {a0.x, a0.y, a0.z, a0.w, a1.x, a1.y, a1.z, a1.w};
    float xsB[8] = {b0.x, b0.y, b0.z, b0.w, b1.x, b1.y, b1.z, b1.w};

    // Row stats.
    float smA = 0.f, sqA = 0.f, smB = 0.f, sqB = 0.f;
    #pragma unroll
    for (int i = 0; i < 8; ++i) {
        smA += xsA[i]; sqA = fmaf(xsA[i], xsA[i], sqA);
        smB += xsB[i]; sqB = fmaf(xsB[i], xsB[i], sqB);
    }
    warp_sum4(smA, sqA, smB, sqB);

    const float mA = smA * (1.0f / BN_D), mB = smB * (1.0f / BN_D);
    const float cA = sqrtf(fmaxf(fmaf(-smA, mA, sqA), 0.f));  // max|x-m| <= c
    const float cB = sqrtf(fmaxf(fmaf(-smB, mB, sqB), 0.f));
    const float loA = -mA - cA - 7.0f, hiA = -mA + cA + 7.0f; // rigorous bracket
    const float loB = -mB - cB - 7.0f, hiB = -mB + cB + 7.0f;
    const float varA = fmaxf(sqA * (1.0f / BN_D) - mA * mA, 0.f);
    const float varB = fmaxf(sqB * (1.0f / BN_D) - mB * mB, 0.f);
    const float g2A = fmaf(0.3926991f, varA, 1.0f), g2B = fmaf(0.3926991f, varB, 1.0f);
    const float rsA = rsqrtf(g2A), rsB = rsqrtf(g2B);
    float nuA = fmaf(-1.0986123f * g2A, rsA, -mA);   // -m - ln3*sqrt(g2)
    float nuB = fmaf(-1.0986123f * g2B, rsB, -mB);
    nuA = fminf(fmaxf(nuA, loA), hiA);
    nuB = fminf(fmaxf(nuB, loB), hiB);
    const float fp0A = 48.0f * rsA, fp0B = 48.0f * rsB;  // analytic slope

    float sA[8], sB[8];
    float fA, qA, fB, qB;

    // Pass 1: Newton with analytic slope (f only).
    fA = 0.f; qA = 0.f; fB = 0.f; qB = 0.f;
    sig8<false>(xsA, -L2E * nuA, sA, fA, qA);
    sig8<false>(xsB, -L2E * nuB, sB, fB, qB);
    warp_sum2(fA, fB);
    nuA -= __fdividef(fA - 64.0f, fp0A);
    nuB -= __fdividef(fB - 64.0f, fp0B);
    nuA = fminf(fmaxf(nuA, loA), hiA);
    nuB = fminf(fmaxf(nuB, loB), hiB);

    // Pass 2: accurate step d + 2nd-order Taylor output.
    fA = 0.f; qA = 0.f; fB = 0.f; qB = 0.f;
    sig8<true>(xsA, -L2E * nuA, sA, fA, qA);
    sig8<true>(xsB, -L2E * nuB, sB, fB, qB);
    warp_sum4(fA, qA, fB, qB);
    const float dA = -__fdividef(fA - 64.0f, fA - qA);
    const float dB = -__fdividef(fB - 64.0f, fB - qB);
    const float hA = 0.5f * dA * dA;
    const float hB = 0.5f * dB * dB;

    float rA[8], rB[8];
    #pragma unroll
    for (int i = 0; i < 8; ++i) {
        float pA = sA[i] * (1.0f - sA[i]);
        float pB = sB[i] * (1.0f - sB[i]);
        rA[i] = sA[i] + pA * fmaf(1.0f - 2.0f * sA[i], hA, dA);
        rB[i] = sB[i] + pB * fmaf(1.0f - 2.0f * sB[i], hB, dB);
    }
    float4* __restrict__ oa = reinterpret_cast<float4*>(out + (size_t)rowA * BN_D);
    float4* __restrict__ ob = reinterpret_cast<float4*>(out + (size_t)rowB * BN_D);
    oa[lane]      = make_float4(rA[0], rA[1], rA[2], rA[3]);
    oa[lane + 32] = make_float4(rA[4], rA[5], rA[6], rA[7]);
    ob[lane]      = make_float4(rB[0], rB[1], rB[2], rB[3]);
    ob[lane + 32] = make_float4(rB[4], rB[5], rB[6], rB[7]);
}

extern "C" void kernel_launch(void* const* d_in, const int* in_sizes, int n_in,
                              void* d_out, int out_size) {
    const float* x = (const float*)d_in[0];
    float* out = (float*)d_out;
    const int B = in_sizes[0] / BN_D;    // 16384 rows
    // 2048 blocks x 4 warps = 8192 warps, 2 rows per warp.
    // launch_bounds(128,14): regs <= 36 -> 14 blocks/SM -> whole grid resident
    // in one wave (148*14 = 2072 >= 2048).
    binnorm_kernel<<<2048, 128>>>(x, out, B);
}

// round 11
// speedup vs baseline: 1.1696x; 1.1696x over previous
#include <cuda_runtime.h>

// BinNormTrain: per-row nu s.t. sum_d sigmoid(x[d]+nu) == 64; out = sigmoid(x+nu).
// R11 = R8 algorithm (2-row ILP, warm start -> Newton -> accurate step +
// 2nd-order Taylor output) with:
//  (a) persistent grid: 1776 blocks = 148 SMs x 12 resident (natural 40-reg
//      residency; launch_bounds(128,12) permits 42 regs -> NO spill, unlike
//      R10's min_blocks=14 which forced 32 regs and spilled). Warps grid-stride
//      over row-pairs -> the 1.15-wave tail becomes one pair spread over all SMs.
//  (b) var=1 warm start (rows are unit-variance): drops sq accumulation, half
//      the stats reduction, sqrt/rsqrt, and makes pass-1's Newton step a
//      constant multiply. 2-pass Newton absorbs the slightly looser start.

#ifndef BN_D
#define BN_D 256
#endif

static __device__ __forceinline__ float ex2_approx(float a) {
    float r; asm("ex2.approx.ftz.f32 %0, %1;" : "=f"(r) : "f"(a)); return r;
}
static __device__ __forceinline__ float rcp_approx(float a) {
    float r; asm("rcp.approx.ftz.f32 %0, %1;" : "=f"(r) : "f"(a)); return r;
}

static __device__ __forceinline__ void warp_sum2(float& a, float& b) {
    #pragma unroll
    for (int o = 16; o > 0; o >>= 1) {
        a += __shfl_xor_sync(0xFFFFFFFFu, a, o);
        b += __shfl_xor_sync(0xFFFFFFFFu, b, o);
    }
}
static __device__ __forceinline__ void warp_sum4(float& a, float& b, float& c, float& d) {
    #pragma unroll
    for (int o = 16; o > 0; o >>= 1) {
        a += __shfl_xor_sync(0xFFFFFFFFu, a, o);
        b += __shfl_xor_sync(0xFFFFFFFFu, b, o);
        c += __shfl_xor_sync(0xFFFFFFFFu, c, o);
        d += __shfl_xor_sync(0xFFFFFFFFu, d, o);
    }
}

// Quad-rational sigmoids of (xs[i]+nu): 8 EX2 + 2 RCP; accumulates f (and q).
template <bool WithQ>
static __device__ __forceinline__ void sig8(const float* xs, float nl2e,
                                            float* s, float& f, float& q) {
    const float L2E = 1.44269504f;
    #pragma unroll
    for (int b = 0; b < 8; b += 4) {
        float t0 = ex2_approx(fmaf(xs[b+0], -L2E, nl2e));
        float t1 = ex2_approx(fmaf(xs[b+1], -L2E, nl2e));
        float t2 = ex2_approx(fmaf(xs[b+2], -L2E, nl2e));
        float t3 = ex2_approx(fmaf(xs[b+3], -L2E, nl2e));
        float u0 = 1.f + t0, u1 = 1.f + t1, u2 = 1.f + t2, u3 = 1.f + t3;
        float p01 = u0 * u1, p23 = u2 * u3;
        float rq  = rcp_approx(p01 * p23);
        float t01 = p23 * rq, t23 = p01 * rq;
        float s0 = u1 * t01, s1 = u0 * t01;
        float s2 = u3 * t23, s3 = u2 * t23;
        s[b+0] = s0; s[b+1] = s1; s[b+2] = s2; s[b+3] = s3;
        f += (s0 + s1) + (s2 + s3);
        if (WithQ) {
            q = fmaf(s0, s0, q); q = fmaf(s1, s1, q);
            q = fmaf(s2, s2, q); q = fmaf(s3, s3, q);
        }
    }
}

__global__ __launch_bounds__(128, 12)
void binnorm_kernel(const float* __restrict__ x, float* __restrict__ out, int B) {
    const int lane    = threadIdx.x & 31;
    const int warp0   = (blockIdx.x * blockDim.x + threadIdx.x) >> 5;
    const int totw    = (gridDim.x * blockDim.x) >> 5;   // 7104
    const int npairs  = B >> 1;                          // 8192
    const float L2E = 1.44269504f;
    // var=1 warm-start constants: g2 = 1 + pi/8, nu0 = -m - ln3*sqrt(g2),
    // slope fp0 = 48/sqrt(g2).
    const float NU_OFF   = 1.2965426f;    // ln3*sqrt(1.3926991)
    const float INV_FP0  = 0.02458613f;   // sqrt(1.3926991)/48

    for (int p = warp0; p < npairs; p += totw) {
        const int rowA = p;
        const int rowB = p + npairs;

        const float4* __restrict__ xa = reinterpret_cast<const float4*>(x + (size_t)rowA * BN_D);
        const float4* __restrict__ xb = reinterpret_cast<const float4*>(x + (size_t)rowB * BN_D);
        float4 a0 = xa[lane], a1 = xa[lane + 32];
        float4 b0 = xb[lane], b1 = xb[lane + 32];
        float xsA[8] = {a0.x, a0.y, a0.z, a0.w, a1.x, a1.y, a1.z, a1.w};
        float xsB[8] = {b0.x, b0.y, b0.z, b0.w, b1.x, b1.y, b1.z, b1.w};

        // Row means only.
        float smA = 0.f, smB = 0.f;
        #pragma unroll
        for (int i = 0; i < 8; ++i) { smA += xsA[i]; smB += xsB[i]; }
        warp_sum2(smA, smB);
        const float mA = smA * (1.0f / BN_D), mB = smB * (1.0f / BN_D);

        float nuA = -mA - NU_OFF;
        float nuB = -mB - NU_OFF;

        float sA[8], sB[8];
        float fA, qA, fB, qB;

        // Pass 1: Newton with constant analytic slope (f only).
        fA = 0.f; qA = 0.f; fB = 0.f; qB = 0.f;
        sig8<false>(xsA, -L2E * nuA, sA, fA, qA);
        sig8<false>(xsB, -L2E * nuB, sB, fB, qB);
        warp_sum2(fA, fB);
        nuA -= (fA - 64.0f) * INV_FP0;
        nuB -= (fB - 64.0f) * INV_FP0;
        // Wide safety clamp (never binds on sane data).
        nuA = fminf(fmaxf(nuA, -mA - 37.0f), -mA + 37.0f);
        nuB = fminf(fmaxf(nuB, -mB - 37.0f), -mB + 37.0f);

        // Pass 2: accurate step d + 2nd-order Taylor output.
        fA = 0.f; qA = 0.f; fB = 0.f; qB = 0.f;
        sig8<true>(xsA, -L2E * nuA, sA, fA, qA);
        sig8<true>(xsB, -L2E * nuB, sB, fB, qB);
        warp_sum4(fA, qA, fB, qB);
        const float dA = -__fdividef(fA - 64.0f, fA - qA);
        const float dB = -__fdividef(fB - 64.0f, fB - qB);
        const float hA = 0.5f * dA * dA;
        const float hB = 0.5f * dB * dB;

        float rA[8], rB[8];
        #pragma unroll
        for (int i = 0; i < 8; ++i) {
            float pA = sA[i] * (1.0f - sA[i]);
            float pB = sB[i] * (1.0f - sB[i]);
            rA[i] = sA[i] + pA * fmaf(1.0f - 2.0f * sA[i], hA, dA);
            rB[i] = sB[i] + pB * fmaf(1.0f - 2.0f * sB[i], hB, dB);
        }
        float4* __restrict__ oa = reinterpret_cast<float4*>(out + (size_t)rowA * BN_D);
        float4* __restrict__ ob = reinterpret_cast<float4*>(out + (size_t)rowB * BN_D);
        oa[lane]      = make_float4(rA[0], rA[1], rA[2], rA[3]);
        oa[lane + 32] = make_float4(rA[4], rA[5], rA[6], rA[7]);
        ob[lane]      = make_float4(rB[0], rB[1], rB[2], rB[3]);
        ob[lane + 32] = make_float4(rB[4], rB[5], rB[6], rB[7]);
    }
}

extern "C" void kernel_launch(void* const* d_in, const int* in_sizes, int n_in,
                              void* d_out, int out_size) {
    const float* x = (const float*)d_in[0];
    float* out = (float*)d_out;
    const int B = in_sizes[0] / BN_D;    // 16384 rows -> 8192 pairs
    // Persistent: 148 SMs x 12 resident blocks = 1776 blocks (7104 warps),
    // grid-striding over 8192 pairs. One launch wave, tail spread across SMs.
    binnorm_kernel<<<1776, 128>>>(x, out, B);
}

// round 12
// speedup vs baseline: 1.4172x; 1.2117x over previous
#include <cuda_runtime.h>

// BinNormTrain: per-row nu s.t. sum_d sigmoid(x[d]+nu) == 64; out = sigmoid(x+nu).
// R12 = R8 launch structure (2048 blocks x 128, ONE pair per warp, loads
// front-batched, no persistent loop — R11 proved the loop costs ~3us) combined
// with R11's validated-cheap math (mean-only stats, var=1 constant-slope
// pass-1 Newton; rel_err measured identical to full-stats version):
//   warm start -> Newton(const slope) -> pass with accurate step d and
//   2nd-order Taylor output  r = s + p d + 0.5 p (1-2s) d^2.

#ifndef BN_D
#define BN_D 256
#endif

static __device__ __forceinline__ float ex2_approx(float a) {
    float r; asm("ex2.approx.ftz.f32 %0, %1;" : "=f"(r) : "f"(a)); return r;
}
static __device__ __forceinline__ float rcp_approx(float a) {
    float r; asm("rcp.approx.ftz.f32 %0, %1;" : "=f"(r) : "f"(a)); return r;
}

static __device__ __forceinline__ void warp_sum2(float& a, float& b) {
    #pragma unroll
    for (int o = 16; o > 0; o >>= 1) {
        a += __shfl_xor_sync(0xFFFFFFFFu, a, o);
        b += __shfl_xor_sync(0xFFFFFFFFu, b, o);
    }
}
static __device__ __forceinline__ void warp_sum4(float& a, float& b, float& c, float& d) {
    #pragma unroll
    for (int o = 16; o > 0; o >>= 1) {
        a += __shfl_xor_sync(0xFFFFFFFFu, a, o);
        b += __shfl_xor_sync(0xFFFFFFFFu, b, o);
        c += __shfl_xor_sync(0xFFFFFFFFu, c, o);
        d += __shfl_xor_sync(0xFFFFFFFFu, d, o);
    }
}

// Quad-rational sigmoids of (xs[i]+nu): 8 EX2 + 2 RCP; accumulates f (and q).
template <bool WithQ>
static __device__ __forceinline__ void sig8(const float* xs, float nl2e,
                                            float* s, float& f, float& q) {
    const float L2E = 1.44269504f;
    #pragma unroll
    for (int b = 0; b < 8; b += 4) {
        float t0 = ex2_approx(fmaf(xs[b+0], -L2E, nl2e));
        float t1 = ex2_approx(fmaf(xs[b+1], -L2E, nl2e));
        float t2 = ex2_approx(fmaf(xs[b+2], -L2E, nl2e));
        float t3 = ex2_approx(fmaf(xs[b+3], -L2E, nl2e));
        float u0 = 1.f + t0, u1 = 1.f + t1, u2 = 1.f + t2, u3 = 1.f + t3;
        float p01 = u0 * u1, p23 = u2 * u3;
        float rq  = rcp_approx(p01 * p23);
        float t01 = p23 * rq, t23 = p01 * rq;
        float s0 = u1 * t01, s1 = u0 * t01;
        float s2 = u3 * t23, s3 = u2 * t23;
        s[b+0] = s0; s[b+1] = s1; s[b+2] = s2; s[b+3] = s3;
        f += (s0 + s1) + (s2 + s3);
        if (WithQ) {
            q = fmaf(s0, s0, q); q = fmaf(s1, s1, q);
            q = fmaf(s2, s2, q); q = fmaf(s3, s3, q);
        }
    }
}

__global__ __launch_bounds__(128)
void binnorm_kernel(const float* __restrict__ x, float* __restrict__ out, int B) {
    const int lane   = threadIdx.x & 31;
    const int warp0  = (blockIdx.x * blockDim.x + threadIdx.x) >> 5;
    const int nwarps = (gridDim.x * blockDim.x) >> 5;   // 8192
    const float L2E = 1.44269504f;
    // var=1 warm-start constants (validated in R11: rel_err unchanged):
    const float NU_OFF  = 1.2965426f;     // ln3*sqrt(1+pi/8)
    const float INV_FP0 = 0.02458613f;    // sqrt(1+pi/8)/48

    // Each warp owns rows {warp0, warp0 + nwarps}; B == 2*nwarps here (16384).
    const int rowA = warp0;
    int rowB = warp0 + nwarps;
    if (rowA >= B) return;                 // uniform
    if (rowB >= B) rowB = rowA;            // degenerate duplicate; still correct

    const float4* __restrict__ xa = reinterpret_cast<const float4*>(x + (size_t)rowA * BN_D);
    const float4* __restrict__ xb = reinterpret_cast<const float4*>(x + (size_t)rowB * BN_D);
    float4 a0 = xa[lane], a1 = xa[lane + 32];
    float4 b0 = xb[lane], b1 = xb[lane + 32];
    float xsA[8] = {a0.x, a0.y, a0.z, a0.w, a1.x, a1.y, a1.z, a1.w};
    float xsB[8] = {b0.x, b0.y, b0.z, b0.w, b1.x, b1.y, b1.z, b1.w};

    // Row means only.
    float smA = 0.f, smB = 0.f;
    #pragma unroll
    for (int i = 0; i < 8; ++i) { smA += xsA[i]; smB += xsB[i]; }
    warp_sum2(smA, smB);
    const float mA = smA * (1.0f / BN_D), mB = smB * (1.0f / BN_D);

    float nuA = -mA - NU_OFF;
    float nuB = -mB - NU_OFF;

    float sA[8], sB[8];
    float fA, qA, fB, qB;

    // Pass 1: Newton with constant analytic slope (f only).
    fA = 0.f; qA = 0.f; fB = 0.f; qB = 0.f;
    sig8<false>(xsA, -L2E * nuA, sA, fA, qA);
    sig8<false>(xsB, -L2E * nuB, sB, fB, qB);
    warp_sum2(fA, fB);
    nuA -= (fA - 64.0f) * INV_FP0;
    nuB -= (fB - 64.0f) * INV_FP0;
    // Wide safety clamp (never binds on sane data; keeps pass-2 args finite).
    nuA = fminf(fmaxf(nuA, -mA - 37.0f), -mA + 37.0f);
    nuB = fminf(fmaxf(nuB, -mB - 37.0f), -mB + 37.0f);

    // Pass 2: accurate step d + 2nd-order Taylor output.
    fA = 0.f; qA = 0.f; fB = 0.f; qB = 0.f;
    sig8<true>(xsA, -L2E * nuA, sA, fA, qA);
    sig8<true>(xsB, -L2E * nuB, sB, fB, qB);
    warp_sum4(fA, qA, fB, qB);
    const float dA = -__fdividef(fA - 64.0f, fA - qA);
    const float dB = -__fdividef(fB - 64.0f, fB - qB);
    const float hA = 0.5f * dA * dA;
    const float hB = 0.5f * dB * dB;

    float rA[8], rB[8];
    #pragma unroll
    for (int i = 0; i < 8; ++i) {
        float pA = sA[i] * (1.0f - sA[i]);
        float pB = sB[i] * (1.0f - sB[i]);
        rA[i] = sA[i] + pA * fmaf(1.0f - 2.0f * sA[i], hA, dA);
        rB[i] = sB[i] + pB * fmaf(1.0f - 2.0f * sB[i], hB, dB);
    }
    float4* __restrict__ oa = reinterpret_cast<float4*>(out + (size_t)rowA * BN_D);
    float4* __restrict__ ob = reinterpret_cast<float4*>(out + (size_t)rowB * BN_D);
    oa[lane]      = make_float4(rA[0], rA[1], rA[2], rA[3]);
    oa[lane + 32] = make_float4(rA[4], rA[5], rA[6], rA[7]);
    ob[lane]      = make_float4(rB[0], rB[1], rB[2], rB[3]);
    ob[lane + 32] = make_float4(rB[4], rB[5], rB[6], rB[7]);
}

extern "C" void kernel_launch(void* const* d_in, const int* in_sizes, int n_in,
                              void* d_out, int out_size) {
    const float* x = (const float*)d_in[0];
    float* out = (float*)d_out;
    const int B = in_sizes[0] / BN_D;    // 16384 rows
    // R8 shape: 2048 blocks x 4 warps = 8192 warps, one row-pair per warp,
    // all loads issued at kernel entry (max MLP). No persistent loop.
    binnorm_kernel<<<2048, 128>>>(x, out, B);
}

// round 13
// speedup vs baseline: 1.5768x; 1.1126x over previous
#include <cuda_runtime.h>

// BinNormTrain: per-row nu s.t. sum_d sigmoid(x[d]+nu) == 64; out = sigmoid(x+nu).
// R13 = R12 math (mean-only warm start -> Newton(const slope) -> accurate step +
// 2nd-order Taylor output) with HALF-WARP row ownership: lanes 0-15 own row A
// (16 elems/lane), lanes 16-31 own row B. Butterfly over offsets {8,4,2,1}
// reduces BOTH rows in one 4-deep chain (bit 4 never flips), cutting the three
// reduction rounds from 80 instr to 24 and deduplicating per-row scalar math.
// Pass-2 sigmoids overwrite xs in place to keep regs ~32 (single-wave residency).

#ifndef BN_D
#define BN_D 256
#endif

static __device__ __forceinline__ float ex2_approx(float a) {
    float r; asm("ex2.approx.ftz.f32 %0, %1;" : "=f"(r) : "f"(a)); return r;
}
static __device__ __forceinline__ float rcp_approx(float a) {
    float r; asm("rcp.approx.ftz.f32 %0, %1;" : "=f"(r) : "f"(a)); return r;
}

// Sum within each 16-lane half (offsets < 16 never cross halves).
static __device__ __forceinline__ float half_sum(float v) {
    #pragma unroll
    for (int o = 8; o > 0; o >>= 1) v += __shfl_xor_sync(0xFFFFFFFFu, v, o);
    return v;
}
static __device__ __forceinline__ void half_sum2(float& a, float& b) {
    #pragma unroll
    for (int o = 8; o > 0; o >>= 1) {
        a += __shfl_xor_sync(0xFFFFFFFFu, a, o);
        b += __shfl_xor_sync(0xFFFFFFFFu, b, o);
    }
}

__global__ __launch_bounds__(128)
void binnorm_kernel(const float* __restrict__ x, float* __restrict__ out, int B) {
    const int lane   = threadIdx.x & 31;
    const int hl     = lane & 15;                       // lane within half-warp
    const int warp0  = (blockIdx.x * blockDim.x + threadIdx.x) >> 5;
    const int nwarps = (gridDim.x * blockDim.x) >> 5;   // 8192
    const float L2E = 1.44269504f;
    const float NU_OFF  = 1.2965426f;     // ln3*sqrt(1+pi/8)   (var=1 warm start)
    const float INV_FP0 = 0.02458613f;    // sqrt(1+pi/8)/48

    if (warp0 >= B) return;                             // uniform
    int row = (lane & 16) ? (warp0 + nwarps) : warp0;   // half-warp's row
    if (row >= B) row = warp0;                          // degenerate guard

    const float4* __restrict__ xr = reinterpret_cast<const float4*>(x + (size_t)row * BN_D);
    float4 v0 = xr[hl];        // each half-warp covers its row's 64 float4s
    float4 v1 = xr[hl + 16];
    float4 v2 = xr[hl + 32];
    float4 v3 = xr[hl + 48];
    float xs[16] = {v0.x, v0.y, v0.z, v0.w, v1.x, v1.y, v1.z, v1.w,
                    v2.x, v2.y, v2.z, v2.w, v3.x, v3.y, v3.z, v3.w};

    // Row mean (one 4-deep chain serves both rows).
    float sm = 0.f;
    #pragma unroll
    for (int i = 0; i < 16; ++i) sm += xs[i];
    sm = half_sum(sm);
    const float m = sm * (1.0f / BN_D);

    float nu = -m - NU_OFF;

    // Pass 1: f only, Newton with constant analytic slope.
    {
        const float nl2e = -L2E * nu;
        float f = 0.f;
        #pragma unroll
        for (int b = 0; b < 16; b += 4) {
            float t0 = ex2_approx(fmaf(xs[b+0], -L2E, nl2e));
            float t1 = ex2_approx(fmaf(xs[b+1], -L2E, nl2e));
            float t2 = ex2_approx(fmaf(xs[b+2], -L2E, nl2e));
            float t3 = ex2_approx(fmaf(xs[b+3], -L2E, nl2e));
            float u0 = 1.f + t0, u1 = 1.f + t1, u2 = 1.f + t2, u3 = 1.f + t3;
            float p01 = u0 * u1, p23 = u2 * u3;
            float rq  = rcp_approx(p01 * p23);
            float t01 = p23 * rq, t23 = p01 * rq;
            f += (u1 * t01 + u0 * t01) + (u3 * t23 + u2 * t23);
        }
        f = half_sum(f);
        nu -= (f - 64.0f) * INV_FP0;
        nu = fminf(fmaxf(nu, -m - 37.0f), -m + 37.0f);  // wide safety clamp
    }

    // Pass 2: sigmoids (written in place over xs), accurate step d,
    // 2nd-order Taylor output  r = s + p*(d + (1-2s)*d^2/2).
    float f = 0.f, q = 0.f;
    {
        const float nl2e = -L2E * nu;
        #pragma unroll
        for (int b = 0; b < 16; b += 4) {
            float t0 = ex2_approx(fmaf(xs[b+0], -L2E, nl2e));
            float t1 = ex2_approx(fmaf(xs[b+1], -L2E, nl2e));
            float t2 = ex2_approx(fmaf(xs[b+2], -L2E, nl2e));
            float t3 = ex2_approx(fmaf(xs[b+3], -L2E, nl2e));
            float u0 = 1.f + t0, u1 = 1.f + t1, u2 = 1.f + t2, u3 = 1.f + t3;
            float p01 = u0 * u1, p23 = u2 * u3;
            float rq  = rcp_approx(p01 * p23);
            float t01 = p23 * rq, t23 = p01 * rq;
            float s0 = u1 * t01, s1 = u0 * t01;
            float s2 = u3 * t23, s3 = u2 * t23;
            xs[b+0] = s0; xs[b+1] = s1; xs[b+2] = s2; xs[b+3] = s3;  // in place
            f += (s0 + s1) + (s2 + s3);
            q = fmaf(s0, s0, q); q = fmaf(s1, s1, q);
            q = fmaf(s2, s2, q); q = fmaf(s3, s3, q);
        }
    }
    half_sum2(f, q);
    const float d = -__fdividef(f - 64.0f, f - q);   // f - q = sum s(1-s) > 0
    const float h = 0.5f * d * d;

    float4* __restrict__ orow = reinterpret_cast<float4*>(out + (size_t)row * BN_D);
    float r[16];
    #pragma unroll
    for (int i = 0; i < 16; ++i) {
        float s = xs[i];
        float p = s * (1.0f - s);
        r[i] = s + p * fmaf(1.0f - 2.0f * s, h, d);
    }
    orow[hl]      = make_float4(r[0],  r[1],  r[2],  r[3]);
    orow[hl + 16] = make_float4(r[4],  r[5],  r[6],  r[7]);
    orow[hl + 32] = make_float4(r[8],  r[9],  r[10], r[11]);
    orow[hl + 48] = make_float4(r[12], r[13], r[14], r[15]);
}

extern "C" void kernel_launch(void* const* d_in, const int* in_sizes, int n_in,
                              void* d_out, int out_size) {
    const float* x = (const float*)d_in[0];
    float* out = (float*)d_out;
    const int B = in_sizes[0] / BN_D;    // 16384 rows
    // 2048 blocks x 4 warps = 8192 warps; each warp = 2 half-warps = 2 rows.
    binnorm_kernel<<<2048, 128>>>(x, out, B);
}

// round 14
// speedup vs baseline: 1.7048x; 1.0812x over previous
#include <cuda_runtime.h>

// BinNormTrain: per-row nu s.t. sum_d sigmoid(x[d]+nu) == 64; out = sigmoid(x+nu).
// R14: single-pass solver. Variance-aware warm start (e0 <~ 0.05, R8-validated)
// -> ONE sigmoid pass accumulating f=Σs, q=Σs², c=Σs³
// -> Halley step (cubic): F'=f-q, F''=f-3q+2c, d = dN/(1+0.5 dN F''/F')
// -> 2nd-order Taylor output r = s + p(d + (1-2s)d²/2)  at nu0+d.
// Removes R13's entire pass-1 (16 EX2+4 RCP+reduction+step serialization stage).
// Half-warp row ownership retained: lanes 0-15 = row A, 16-31 = row B,
// 16 elems/lane, 4-deep shared butterfly reductions.

#ifndef BN_D
#define BN_D 256
#endif

static __device__ __forceinline__ float ex2_approx(float a) {
    float r; asm("ex2.approx.ftz.f32 %0, %1;" : "=f"(r) : "f"(a)); return r;
}
static __device__ __forceinline__ float rcp_approx(float a) {
    float r; asm("rcp.approx.ftz.f32 %0, %1;" : "=f"(r) : "f"(a)); return r;
}

// Per-half-warp reductions (offsets < 16 never cross the two rows).
static __device__ __forceinline__ void half_sum2(float& a, float& b) {
    #pragma unroll
    for (int o = 8; o > 0; o >>= 1) {
        a += __shfl_xor_sync(0xFFFFFFFFu, a, o);
        b += __shfl_xor_sync(0xFFFFFFFFu, b, o);
    }
}
static __device__ __forceinline__ void half_sum3(float& a, float& b, float& c) {
    #pragma unroll
    for (int o = 8; o > 0; o >>= 1) {
        a += __shfl_xor_sync(0xFFFFFFFFu, a, o);
        b += __shfl_xor_sync(0xFFFFFFFFu, b, o);
        c += __shfl_xor_sync(0xFFFFFFFFu, c, o);
    }
}

__global__ __launch_bounds__(128)
void binnorm_kernel(const float* __restrict__ x, float* __restrict__ out, int B) {
    const int lane   = threadIdx.x & 31;
    const int hl     = lane & 15;
    const int warp0  = (blockIdx.x * blockDim.x + threadIdx.x) >> 5;
    const int nwarps = (gridDim.x * blockDim.x) >> 5;   // 8192
    const float L2E = 1.44269504f;

    if (warp0 >= B) return;                              // uniform
    int row = (lane & 16) ? (warp0 + nwarps) : warp0;
    if (row >= B) row = warp0;

    const float4* __restrict__ xr = reinterpret_cast<const float4*>(x + (size_t)row * BN_D);
    float4 v0 = xr[hl];
    float4 v1 = xr[hl + 16];
    float4 v2 = xr[hl + 32];
    float4 v3 = xr[hl + 48];
    float xs[16] = {v0.x, v0.y, v0.z, v0.w, v1.x, v1.y, v1.z, v1.w,
                    v2.x, v2.y, v2.z, v2.w, v3.x, v3.y, v3.z, v3.w};

    // Row stats: mean + sumsq (one 4-deep paired chain).
    float sm = 0.f, sq = 0.f;
    #pragma unroll
    for (int i = 0; i < 16; ++i) { sm += xs[i]; sq = fmaf(xs[i], xs[i], sq); }
    half_sum2(sm, sq);
    const float m   = sm * (1.0f / BN_D);
    const float var = fmaxf(sq * (1.0f / BN_D) - m * m, 0.f);
    // Logit-moment warm start: nu0 = -m - ln3*sqrt(1 + pi/8 var)   (e0 <~ 0.05)
    const float g2 = fmaf(0.3926991f, var, 1.0f);
    float nu = -m - 1.0986123f * sqrtf(g2);

    // Single sigmoid pass: s (in place over xs), f=Σs, q=Σs², c=Σs³.
    float f = 0.f, q = 0.f, c = 0.f;
    {
        const float nl2e = -L2E * nu;
        #pragma unroll
        for (int b = 0; b < 16; b += 4) {
            float t0 = ex2_approx(fmaf(xs[b+0], -L2E, nl2e));
            float t1 = ex2_approx(fmaf(xs[b+1], -L2E, nl2e));
            float t2 = ex2_approx(fmaf(xs[b+2], -L2E, nl2e));
            float t3 = ex2_approx(fmaf(xs[b+3], -L2E, nl2e));
            float u0 = 1.f + t0, u1 = 1.f + t1, u2 = 1.f + t2, u3 = 1.f + t3;
            float p01 = u0 * u1, p23 = u2 * u3;
            float rq  = rcp_approx(p01 * p23);
            float t01 = p23 * rq, t23 = p01 * rq;
            float s0 = u1 * t01, s1 = u0 * t01;
            float s2 = u3 * t23, s3 = u2 * t23;
            xs[b+0] = s0; xs[b+1] = s1; xs[b+2] = s2; xs[b+3] = s3;
            f += (s0 + s1) + (s2 + s3);
            float ss0 = s0 * s0, ss1 = s1 * s1, ss2 = s2 * s2, ss3 = s3 * s3;
            q += (ss0 + ss1) + (ss2 + ss3);
            c = fmaf(ss0, s0, c); c = fmaf(ss1, s1, c);
            c = fmaf(ss2, s2, c); c = fmaf(ss3, s3, c);
        }
    }
    half_sum3(f, q, c);

    // Halley step (cubic). F = f-64, F' = f-q > 0, F'' = f - 3q + 2c.
    const float F   = f - 64.0f;
    const float Fp  = f - q;
    const float Fpp = fmaf(2.0f, c, fmaf(-3.0f, q, f));
    const float dN  = -__fdividef(F, Fp);
    float den = fmaf(0.5f * dN, __fdividef(Fpp, Fp), 1.0f);
    // Guard: den ~ 1 +- small; fall back to Newton if it went weird.
    if (!(den > 0.25f)) den = 1.0f;
    float d = __fdividef(dN, den);
    d = fminf(fmaxf(d, -2.0f), 2.0f);     // never binds on sane data
    const float h = 0.5f * d * d;

    // 2nd-order Taylor output at nu0 + d.
    float4* __restrict__ orow = reinterpret_cast<float4*>(out + (size_t)row * BN_D);
    float r[16];
    #pragma unroll
    for (int i = 0; i < 16; ++i) {
        float s = xs[i];
        float p = s * (1.0f - s);
        r[i] = s + p * fmaf(1.0f - 2.0f * s, h, d);
    }
    orow[hl]      = make_float4(r[0],  r[1],  r[2],  r[3]);
    orow[hl + 16] = make_float4(r[4],  r[5],  r[6],  r[7]);
    orow[hl + 32] = make_float4(r[8],  r[9],  r[10], r[11]);
    orow[hl + 48] = make_float4(r[12], r[13], r[14], r[15]);
}

extern "C" void kernel_launch(void* const* d_in, const int* in_sizes, int n_in,
                              void* d_out, int out_size) {
    const float* x = (const float*)d_in[0];
    float* out = (float*)d_out;
    const int B = in_sizes[0] / BN_D;    // 16384 rows
    // 2048 blocks x 4 warps = 8192 warps; each warp = 2 half-warps = 2 rows.
    binnorm_kernel<<<2048, 128>>>(x, out, B);
}